// round 3
// baseline (speedup 1.0000x reference)
#include <cuda_runtime.h>

#define N_NODE  256
#define IN_DIM  256
#define LAT     8192
#define OUT_DIM 2048
#define KSPLIT  4

// Scratch (device globals: allocation-free rule)
__device__ float g_h[N_NODE * LAT];                 // 8 MB: relu(adj@W1+b1)
__device__ float g_part[KSPLIT][N_NODE * OUT_DIM];  // 8 MB: GEMM2 K-split partials
__device__ float g_p0[N_NODE * OUT_DIM];            // 2 MB: exp(keys0/2)

// ---------------------------------------------------------------------------
// SGEMM: 64x64 tile, BK=16, 256 threads, 4x4 per thread, smem double-buffer.
// MODE 0: C = relu(A@B + bias) -> g_h      (A = Aext = adj)
// MODE 1: raw partial A@B -> g_part[blockIdx.z]  (A = g_h)
// ---------------------------------------------------------------------------
template<int MODE>
__global__ void __launch_bounds__(256)
sgemm_kernel(const float* __restrict__ Aext,
             const float* __restrict__ B,
             const float* __restrict__ bias,
             int N, int Ksub, int lda)
{
    const float* A = (MODE == 0) ? Aext : (const float*)g_h;
    __shared__ float As[2][16][64];
    __shared__ float Bs[2][16][64];

    const int tid = threadIdx.x;
    const int bm  = blockIdx.y * 64;
    const int bn  = blockIdx.x * 64;
    const int kOff = (MODE == 1) ? (int)blockIdx.z * Ksub : 0;

    const int arow = tid >> 2;            // 0..63
    const int acol = (tid & 3) << 2;      // 0,4,8,12
    const int brow = tid >> 4;            // 0..15
    const int bcol = (tid & 15) << 2;     // 0..60

    const float* Aptr = A + (size_t)(bm + arow) * lda + kOff + acol;
    const float* Bptr = B + (size_t)(kOff + brow) * N + bn + bcol;

    float4 aReg = *(const float4*)Aptr;
    float4 bReg = *(const float4*)Bptr;
    As[0][acol + 0][arow] = aReg.x;
    As[0][acol + 1][arow] = aReg.y;
    As[0][acol + 2][arow] = aReg.z;
    As[0][acol + 3][arow] = aReg.w;
    *(float4*)&Bs[0][brow][bcol] = bReg;
    __syncthreads();

    float acc[4][4];
#pragma unroll
    for (int i = 0; i < 4; i++)
#pragma unroll
        for (int j = 0; j < 4; j++) acc[i][j] = 0.f;

    const int tx = tid & 15, ty = tid >> 4;
    const int nT = Ksub >> 4;

    for (int t = 0; t < nT; ++t) {
        const int cur = t & 1;
        if (t + 1 < nT) {
            aReg = *(const float4*)(Aptr + (t + 1) * 16);
            bReg = *(const float4*)(Bptr + (size_t)(t + 1) * 16 * N);
        }
#pragma unroll
        for (int k = 0; k < 16; ++k) {
            float ar[4], br[4];
            *(float4*)ar = *(const float4*)&As[cur][k][ty << 2];
            *(float4*)br = *(const float4*)&Bs[cur][k][tx << 2];
#pragma unroll
            for (int i = 0; i < 4; i++)
#pragma unroll
                for (int j = 0; j < 4; j++)
                    acc[i][j] += ar[i] * br[j];
        }
        if (t + 1 < nT) {
            const int nxt = cur ^ 1;
            As[nxt][acol + 0][arow] = aReg.x;
            As[nxt][acol + 1][arow] = aReg.y;
            As[nxt][acol + 2][arow] = aReg.z;
            As[nxt][acol + 3][arow] = aReg.w;
            *(float4*)&Bs[nxt][brow][bcol] = bReg;
        }
        __syncthreads();
    }

    if (MODE == 0) {
        float4 bv = *(const float4*)&bias[bn + (tx << 2)];
#pragma unroll
        for (int i = 0; i < 4; i++) {
            const int row = bm + (ty << 2) + i;
            float4 o;
            o.x = fmaxf(acc[i][0] + bv.x, 0.f);
            o.y = fmaxf(acc[i][1] + bv.y, 0.f);
            o.z = fmaxf(acc[i][2] + bv.z, 0.f);
            o.w = fmaxf(acc[i][3] + bv.w, 0.f);
            *(float4*)(g_h + (size_t)row * N + bn + (tx << 2)) = o;
        }
    } else {
        float* P = g_part[blockIdx.z];
#pragma unroll
        for (int i = 0; i < 4; i++) {
            const int row = bm + (ty << 2) + i;
            float4 o;
            o.x = acc[i][0]; o.y = acc[i][1]; o.z = acc[i][2]; o.w = acc[i][3];
            *(float4*)(P + (size_t)row * N + bn + (tx << 2)) = o;
        }
    }
}

// ---------------------------------------------------------------------------
// p0 = sqrt(relu(sum_partials + b2) + 1e-30) * exp(z/2)
// 524288 elems as 131072 float4 -> grid 512 x 256
// ---------------------------------------------------------------------------
__global__ void __launch_bounds__(256)
p0_kernel(const float* __restrict__ b2, const float* __restrict__ Z)
{
    const int idx = blockIdx.x * 256 + threadIdx.x;     // float4 index
    float4 s = ((const float4*)g_part[0])[idx];
#pragma unroll
    for (int k = 1; k < KSPLIT; k++) {
        float4 t = ((const float4*)g_part[k])[idx];
        s.x += t.x; s.y += t.y; s.z += t.z; s.w += t.w;
    }
    const float4 bv = ((const float4*)b2)[idx & 511];   // 2048/4 = 512 float4/row
    const float4 zv = ((const float4*)Z)[idx];
    float4 o;
    o.x = sqrtf(fmaxf(s.x + bv.x, 0.f) + 1e-30f) * __expf(0.5f * zv.x);
    o.y = sqrtf(fmaxf(s.y + bv.y, 0.f) + 1e-30f) * __expf(0.5f * zv.y);
    o.z = sqrtf(fmaxf(s.z + bv.z, 0.f) + 1e-30f) * __expf(0.5f * zv.z);
    o.w = sqrtf(fmaxf(s.w + bv.w, 0.f) + 1e-30f) * __expf(0.5f * zv.w);
    ((float4*)g_p0)[idx] = o;
}

// ---------------------------------------------------------------------------
// Relaxed top-k in p-space (t=2):
//   p *= sqrt(max(1 - onehot, 1e-20));  onehot = p / sum(p);  khot += onehot
// One CTA per row; 256 threads x 8 elems in registers; one bar.sync per iter
// via double-buffered cross-warp sums.
// ---------------------------------------------------------------------------
__global__ void __launch_bounds__(256)
topm_kernel(float* __restrict__ out)
{
    const int row = blockIdx.x;
    const int tid = threadIdx.x;
    const float4* pr = (const float4*)(g_p0 + (size_t)row * OUT_DIM);

    float p[8], one[8], kh[8];
    {
        float4 v0 = pr[tid * 2];
        float4 v1 = pr[tid * 2 + 1];
        p[0] = v0.x; p[1] = v0.y; p[2] = v0.z; p[3] = v0.w;
        p[4] = v1.x; p[5] = v1.y; p[6] = v1.z; p[7] = v1.w;
    }
#pragma unroll
    for (int j = 0; j < 8; j++) { one[j] = 0.f; kh[j] = 0.f; }

    __shared__ float wsum[2][8];

    for (int it = 0; it < N_NODE; ++it) {
        float loc = 0.f;
#pragma unroll
        for (int j = 0; j < 8; j++) {
            float m = fmaxf(1.0f - one[j], 1e-20f);
            p[j] *= m * __frsqrt_rn(m);   // p *= sqrt(m)
            loc += p[j];
        }
#pragma unroll
        for (int off = 16; off > 0; off >>= 1)
            loc += __shfl_xor_sync(0xffffffffu, loc, off);

        const int buf = it & 1;
        if ((tid & 31) == 0) wsum[buf][tid >> 5] = loc;
        __syncthreads();

        float s = wsum[buf][0];
#pragma unroll
        for (int w = 1; w < 8; w++) s += wsum[buf][w];
        const float inv = __fdividef(1.0f, s);

#pragma unroll
        for (int j = 0; j < 8; j++) {
            one[j] = p[j] * inv;
            kh[j] += one[j];
        }
    }

    float4* orow = (float4*)(out + (size_t)row * OUT_DIM);
    orow[tid * 2]     = make_float4(kh[0], kh[1], kh[2], kh[3]);
    orow[tid * 2 + 1] = make_float4(kh[4], kh[5], kh[6], kh[7]);
}

// ---------------------------------------------------------------------------
extern "C" void kernel_launch(void* const* d_in, const int* in_sizes, int n_in,
                              void* d_out, int out_size)
{
    const float* adj = (const float*)d_in[0];
    const float* W1  = (const float*)d_in[1];
    const float* b1  = (const float*)d_in[2];
    const float* W2  = (const float*)d_in[3];
    const float* b2  = (const float*)d_in[4];
    const float* z   = (const float*)d_in[5];
    float* out = (float*)d_out;

    // Layer 1: g_h = relu(adj @ W1 + b1)   [256, 8192]
    sgemm_kernel<0><<<dim3(LAT / 64, N_NODE / 64), 256>>>(adj, W1, b1, LAT, IN_DIM, IN_DIM);

    // Layer 2 partials: g_part[s] = g_h[:, s*2048:(s+1)*2048] @ W2[s*2048:...]
    sgemm_kernel<1><<<dim3(OUT_DIM / 64, N_NODE / 64, KSPLIT), 256>>>(
        nullptr, W2, nullptr, OUT_DIM, LAT / KSPLIT, LAT);

    // p0 = sqrt(relu(sum + b2) + 1e-30) * exp(z/2)
    p0_kernel<<<512, 256>>>(b2, z);

    // Relaxed top-k accumulation -> out
    topm_kernel<<<N_NODE, 256>>>(out);
}

// round 7
// speedup vs baseline: 2.1569x; 2.1569x over previous
#include <cuda_runtime.h>
#include <cuda_bf16.h>
#include <cstdint>

#define N_NODE  256
#define IN_DIM  256
#define LAT     8192
#define OUT_DIM 2048
#define KSPLIT  4

// ---------------- device scratch (no allocations allowed) -------------------
__device__ __nv_bfloat16 g_ahi[N_NODE * LAT];     // 4 MB  A=relu(adj@W1+b1) hi
__device__ __nv_bfloat16 g_alo[N_NODE * LAT];     // 4 MB  A lo
__device__ __nv_bfloat16 g_bhi[OUT_DIM * LAT];    // 32 MB W2^T hi (K-major)
__device__ __nv_bfloat16 g_blo[OUT_DIM * LAT];    // 32 MB W2^T lo
__device__ float g_part[KSPLIT][N_NODE * OUT_DIM];// 8 MB  GEMM2 K-split partials
__device__ float g_p0[N_NODE * OUT_DIM];          // 2 MB  exp(keys0/2)

// ---------------- helpers (sm_80-level PTX only: NO sm_100a features) -------
__device__ __forceinline__ uint32_t smem_u32(const void* p) {
    uint32_t a;
    asm("{ .reg .u64 t; cvta.to.shared.u64 t, %1; cvt.u32.u64 %0, t; }" : "=r"(a) : "l"(p));
    return a;
}
__device__ __forceinline__ void cpa16(uint32_t s, const void* g) {
    asm volatile("cp.async.cg.shared.global [%0], [%1], 16;" :: "r"(s), "l"(g));
}
#define CP_COMMIT()  asm volatile("cp.async.commit_group;" ::: "memory")
#define CP_WAIT(n)   asm volatile("cp.async.wait_group %0;" :: "n"(n) : "memory")

__device__ __forceinline__ void mma_bf16(float* c, const uint32_t* a, const uint32_t* b) {
    asm volatile(
        "mma.sync.aligned.m16n8k16.row.col.f32.bf16.bf16.f32 "
        "{%0,%1,%2,%3}, {%4,%5,%6,%7}, {%8,%9}, {%0,%1,%2,%3};"
        : "+f"(c[0]), "+f"(c[1]), "+f"(c[2]), "+f"(c[3])
        : "r"(a[0]), "r"(a[1]), "r"(a[2]), "r"(a[3]), "r"(b[0]), "r"(b[1]));
}

// ---------------------------------------------------------------------------
// GEMM1 (SIMT fp32): A = relu(adj @ W1 + b1) -> bf16 hi/lo split
// ---------------------------------------------------------------------------
__global__ void __launch_bounds__(256)
gemm1_kernel(const float* __restrict__ A,
             const float* __restrict__ B,
             const float* __restrict__ bias)
{
    __shared__ float As[2][16][64];
    __shared__ float Bs[2][16][64];
    const int tid = threadIdx.x;
    const int bm  = blockIdx.y * 64;
    const int bn  = blockIdx.x * 64;

    const int arow = tid >> 2, acol = (tid & 3) << 2;
    const int brow = tid >> 4, bcol = (tid & 15) << 2;

    const float* Aptr = A + (size_t)(bm + arow) * IN_DIM + acol;
    const float* Bptr = B + (size_t)brow * LAT + bn + bcol;

    float4 aReg = *(const float4*)Aptr;
    float4 bReg = *(const float4*)Bptr;
    As[0][acol+0][arow] = aReg.x; As[0][acol+1][arow] = aReg.y;
    As[0][acol+2][arow] = aReg.z; As[0][acol+3][arow] = aReg.w;
    *(float4*)&Bs[0][brow][bcol] = bReg;
    __syncthreads();

    float acc[4][4];
#pragma unroll
    for (int i = 0; i < 4; i++)
#pragma unroll
        for (int j = 0; j < 4; j++) acc[i][j] = 0.f;

    const int tx = tid & 15, ty = tid >> 4;
    const int nT = IN_DIM / 16;
    for (int t = 0; t < nT; ++t) {
        const int cur = t & 1;
        if (t + 1 < nT) {
            aReg = *(const float4*)(Aptr + (t + 1) * 16);
            bReg = *(const float4*)(Bptr + (size_t)(t + 1) * 16 * LAT);
        }
#pragma unroll
        for (int k = 0; k < 16; ++k) {
            float ar[4], br[4];
            *(float4*)ar = *(const float4*)&As[cur][k][ty << 2];
            *(float4*)br = *(const float4*)&Bs[cur][k][tx << 2];
#pragma unroll
            for (int i = 0; i < 4; i++)
#pragma unroll
                for (int j = 0; j < 4; j++) acc[i][j] += ar[i] * br[j];
        }
        if (t + 1 < nT) {
            const int nxt = cur ^ 1;
            As[nxt][acol+0][arow] = aReg.x; As[nxt][acol+1][arow] = aReg.y;
            As[nxt][acol+2][arow] = aReg.z; As[nxt][acol+3][arow] = aReg.w;
            *(float4*)&Bs[nxt][brow][bcol] = bReg;
        }
        __syncthreads();
    }

    float4 bv = *(const float4*)&bias[bn + (tx << 2)];
#pragma unroll
    for (int i = 0; i < 4; i++) {
        const int row = bm + (ty << 2) + i;
        float v[4];
        v[0] = fmaxf(acc[i][0] + bv.x, 0.f);
        v[1] = fmaxf(acc[i][1] + bv.y, 0.f);
        v[2] = fmaxf(acc[i][2] + bv.z, 0.f);
        v[3] = fmaxf(acc[i][3] + bv.w, 0.f);
        const size_t base = (size_t)row * LAT + bn + (tx << 2);
#pragma unroll
        for (int j = 0; j < 4; j += 2) {
            __nv_bfloat16 h0 = __float2bfloat16_rn(v[j]);
            __nv_bfloat16 h1 = __float2bfloat16_rn(v[j+1]);
            __nv_bfloat16 l0 = __float2bfloat16_rn(v[j]   - __bfloat162float(h0));
            __nv_bfloat16 l1 = __float2bfloat16_rn(v[j+1] - __bfloat162float(h1));
            __nv_bfloat162 h; h.x = h0; h.y = h1;
            __nv_bfloat162 l; l.x = l0; l.y = l1;
            *(__nv_bfloat162*)(g_ahi + base + j) = h;
            *(__nv_bfloat162*)(g_alo + base + j) = l;
        }
    }
}

// ---------------------------------------------------------------------------
// W2 [8192, 2048] fp32 -> transpose+split -> g_bhi/g_blo [2048, 8192] bf16
// ---------------------------------------------------------------------------
__global__ void __launch_bounds__(256)
w2conv_kernel(const float* __restrict__ W2)
{
    __shared__ float t[32][33];
    const int nb = blockIdx.x * 32;
    const int kb = blockIdx.y * 32;
    const int tx = threadIdx.x, ty = threadIdx.y;
#pragma unroll
    for (int r = 0; r < 4; r++) {
        const int k = ty + r * 8;
        t[k][tx] = W2[(size_t)(kb + k) * OUT_DIM + nb + tx];
    }
    __syncthreads();
#pragma unroll
    for (int r = 0; r < 4; r++) {
        const int n = ty + r * 8;
        const float v = t[tx][n];
        const __nv_bfloat16 h = __float2bfloat16_rn(v);
        const __nv_bfloat16 l = __float2bfloat16_rn(v - __bfloat162float(h));
        const size_t o = (size_t)(nb + n) * LAT + kb + tx;
        g_bhi[o] = h;
        g_blo[o] = l;
    }
}

// ---------------------------------------------------------------------------
// GEMM2 via mma.sync bf16 split: g_part[z] = A[:, kz:kz+2048] @ W2T slice
// CTA tile 128x128, BK=32, cp.async double-buffered, 8 warps (2x4 of 64x32).
// 3-term split precision: Ahi*Bhi + Ahi*Blo + Alo*Bhi.
// ---------------------------------------------------------------------------
#define BM 128
#define BN 128
#define BK 32
#define KPER   (LAT / KSPLIT)   // 2048
#define NSTAGE (KPER / BK)      // 64
#define ROWW   20               // words per smem row: 16 data + 4 pad
#define TILE_B (128 * ROWW * 4) // 10240 bytes per operand tile
#define STG_B  (4 * TILE_B)     // 40960 bytes per stage (Ahi,Alo,Bhi,Blo)
#define G2_SMEM (2 * STG_B)     // 81920

__global__ void __launch_bounds__(256)
gemm2_mma_kernel()
{
    extern __shared__ uint32_t sm[];
    const uint32_t sbase = smem_u32(sm);
    const int tid  = threadIdx.x;
    const int wid  = tid >> 5, lane = tid & 31;
    const int g    = lane >> 2, t = lane & 3;
    const int bn   = blockIdx.x * BN;
    const int bm   = blockIdx.y * BM;
    const int kz   = blockIdx.z * KPER;
    const int wm   = (wid >> 2) * 64;   // 0 or 64
    const int wn   = (wid & 3) * 32;    // 0,32,64,96

    float acc[4][4][4];
#pragma unroll
    for (int i = 0; i < 4; i++)
#pragma unroll
        for (int j = 0; j < 4; j++)
#pragma unroll
            for (int r = 0; r < 4; r++) acc[i][j][r] = 0.f;

    // ---- async loader: 8 x cp.async(16B) per thread per stage ----
    auto load_stage = [&](int s) {
        const int kb = kz + s * BK;
        const uint32_t sb = sbase + (s & 1) * STG_B;
#pragma unroll
        for (int j = 0; j < 2; j++) {
            const int idx = j * 256 + tid;          // 0..511
            const int r = idx >> 2, c16 = idx & 3;
            const uint32_t off = (uint32_t)(r * ROWW + c16 * 4) << 2;
            const size_t gA = (size_t)(bm + r) * LAT + kb + c16 * 8;
            const size_t gB = (size_t)(bn + r) * LAT + kb + c16 * 8;
            cpa16(sb + off,              g_ahi + gA);
            cpa16(sb + TILE_B + off,     g_alo + gA);
            cpa16(sb + 2 * TILE_B + off, g_bhi + gB);
            cpa16(sb + 3 * TILE_B + off, g_blo + gB);
        }
    };

    load_stage(0); CP_COMMIT();

#pragma unroll 1
    for (int s = 0; s < NSTAGE; ++s) {
        if (s + 1 < NSTAGE) { load_stage(s + 1); CP_COMMIT(); CP_WAIT(1); }
        else                { CP_WAIT(0); }
        __syncthreads();

        const uint32_t* Ah = sm + (s & 1) * (STG_B / 4);
        const uint32_t* Al = Ah + TILE_B / 4;
        const uint32_t* Bh = Al + TILE_B / 4;
        const uint32_t* Bl = Bh + TILE_B / 4;

#pragma unroll
        for (int ks = 0; ks < 2; ++ks) {
            const int kw = ks * 8;
            uint32_t bh[4][2], bl[4][2];
#pragma unroll
            for (int j = 0; j < 4; j++) {
                const int rn = (wn + j * 8 + g) * ROWW + kw + t;
                bh[j][0] = Bh[rn];     bh[j][1] = Bh[rn + 4];
                bl[j][0] = Bl[rn];     bl[j][1] = Bl[rn + 4];
            }
#pragma unroll
            for (int i = 0; i < 4; i++) {
                const int r0 = (wm + i * 16 + g)     * ROWW + kw + t;
                const int r1 = (wm + i * 16 + 8 + g) * ROWW + kw + t;
                uint32_t ah[4], al[4];
                ah[0] = Ah[r0]; ah[1] = Ah[r1]; ah[2] = Ah[r0 + 4]; ah[3] = Ah[r1 + 4];
                al[0] = Al[r0]; al[1] = Al[r1]; al[2] = Al[r0 + 4]; al[3] = Al[r1 + 4];
#pragma unroll
                for (int j = 0; j < 4; j++) {
                    mma_bf16(acc[i][j], ah, bh[j]);
                    mma_bf16(acc[i][j], ah, bl[j]);
                    mma_bf16(acc[i][j], al, bh[j]);
                }
            }
        }
        __syncthreads();
    }

    // ---- epilogue: write fp32 partial tile ----
    float* P = g_part[blockIdx.z];
#pragma unroll
    for (int i = 0; i < 4; i++) {
#pragma unroll
        for (int j = 0; j < 4; j++) {
            const int row0 = bm + wm + i * 16 + g;
            const int col  = bn + wn + j * 8 + t * 2;
            float2 v0; v0.x = acc[i][j][0]; v0.y = acc[i][j][1];
            float2 v1; v1.x = acc[i][j][2]; v1.y = acc[i][j][3];
            *(float2*)(P + (size_t)row0 * OUT_DIM + col)       = v0;
            *(float2*)(P + (size_t)(row0 + 8) * OUT_DIM + col) = v1;
        }
    }
}

// ---------------------------------------------------------------------------
// p0 = sqrt(relu(sum_partials + b2) + 1e-30) * exp(z/2)
// ---------------------------------------------------------------------------
__global__ void __launch_bounds__(256)
p0_kernel(const float* __restrict__ b2, const float* __restrict__ Z)
{
    const int idx = blockIdx.x * 256 + threadIdx.x;     // float4 index
    float4 s = ((const float4*)g_part[0])[idx];
#pragma unroll
    for (int k = 1; k < KSPLIT; k++) {
        float4 t = ((const float4*)g_part[k])[idx];
        s.x += t.x; s.y += t.y; s.z += t.z; s.w += t.w;
    }
    const float4 bv = ((const float4*)b2)[idx & 511];
    const float4 zv = ((const float4*)Z)[idx];
    float4 o;
    o.x = sqrtf(fmaxf(s.x + bv.x, 0.f) + 1e-30f) * __expf(0.5f * zv.x);
    o.y = sqrtf(fmaxf(s.y + bv.y, 0.f) + 1e-30f) * __expf(0.5f * zv.y);
    o.z = sqrtf(fmaxf(s.z + bv.z, 0.f) + 1e-30f) * __expf(0.5f * zv.z);
    o.w = sqrtf(fmaxf(s.w + bv.w, 0.f) + 1e-30f) * __expf(0.5f * zv.w);
    ((float4*)g_p0)[idx] = o;
}

// ---------------------------------------------------------------------------
// Relaxed top-k in p-space (t=2).  sqrt(1-y) via 4-term poly for y<=1/16
// (trunc err <= 2.6e-8); exact sqrtf fallback for rare big-y lanes (<=16/row).
// ---------------------------------------------------------------------------
__global__ void __launch_bounds__(256)
topm_kernel(float* __restrict__ out)
{
    const int row = blockIdx.x;
    const int tid = threadIdx.x;
    const float4* pr = (const float4*)(g_p0 + (size_t)row * OUT_DIM);

    float p[8], one[8], kh[8];
    {
        float4 v0 = pr[tid * 2];
        float4 v1 = pr[tid * 2 + 1];
        p[0]=v0.x; p[1]=v0.y; p[2]=v0.z; p[3]=v0.w;
        p[4]=v1.x; p[5]=v1.y; p[6]=v1.z; p[7]=v1.w;
    }
#pragma unroll
    for (int j = 0; j < 8; j++) { one[j] = 0.f; kh[j] = 0.f; }

    __shared__ float wsum[2][8];

    for (int it = 0; it < N_NODE; ++it) {
        float sc[8];
        bool any = false;
#pragma unroll
        for (int j = 0; j < 8; j++) {
            const float y = one[j];
            sc[j] = 1.f - y * (0.5f + y * (0.125f + y * (0.0625f + y * 0.0390625f)));
            any = any || (y > 0.0625f);
        }
        if (__ballot_sync(0xffffffffu, any)) {
#pragma unroll
            for (int j = 0; j < 8; j++)
                if (one[j] > 0.0625f) sc[j] = sqrtf(fmaxf(1.f - one[j], 1e-20f));
        }
#pragma unroll
        for (int j = 0; j < 8; j++) p[j] *= sc[j];

        float loc = ((p[0] + p[1]) + (p[2] + p[3])) + ((p[4] + p[5]) + (p[6] + p[7]));
#pragma unroll
        for (int off = 16; off > 0; off >>= 1)
            loc += __shfl_xor_sync(0xffffffffu, loc, off);

        const int buf = it & 1;
        if ((tid & 31) == 0) wsum[buf][tid >> 5] = loc;
        __syncthreads();

        float4 a = *(float4*)&wsum[buf][0];
        float4 b = *(float4*)&wsum[buf][4];
        const float s = ((a.x + a.y) + (a.z + a.w)) + ((b.x + b.y) + (b.z + b.w));
        const float inv = __fdividef(1.0f, s);

#pragma unroll
        for (int j = 0; j < 8; j++) {
            one[j] = p[j] * inv;
            kh[j] += one[j];
        }
    }

    float4* orow = (float4*)(out + (size_t)row * OUT_DIM);
    orow[tid * 2]     = make_float4(kh[0], kh[1], kh[2], kh[3]);
    orow[tid * 2 + 1] = make_float4(kh[4], kh[5], kh[6], kh[7]);
}

// ---------------------------------------------------------------------------
extern "C" void kernel_launch(void* const* d_in, const int* in_sizes, int n_in,
                              void* d_out, int out_size)
{
    const float* adj = (const float*)d_in[0];
    const float* W1  = (const float*)d_in[1];
    const float* b1  = (const float*)d_in[2];
    const float* W2  = (const float*)d_in[3];
    const float* b2  = (const float*)d_in[4];
    const float* z   = (const float*)d_in[5];
    float* out = (float*)d_out;

    cudaFuncSetAttribute(gemm2_mma_kernel,
                         cudaFuncAttributeMaxDynamicSharedMemorySize, G2_SMEM);

    // W2 -> transposed bf16 hi/lo
    w2conv_kernel<<<dim3(OUT_DIM / 32, LAT / 32), dim3(32, 8)>>>(W2);

    // Layer 1: A = relu(adj @ W1 + b1) -> bf16 hi/lo
    gemm1_kernel<<<dim3(LAT / 64, N_NODE / 64), 256>>>(adj, W1, b1);

    // Layer 2: mma.sync split-bf16, K-split partials
    gemm2_mma_kernel<<<dim3(OUT_DIM / BN, N_NODE / BM, KSPLIT), 256, G2_SMEM>>>();

    // p0
    p0_kernel<<<512, 256>>>(b2, z);

    // top-m
    topm_kernel<<<N_NODE, 256>>>(out);
}

// round 8
// speedup vs baseline: 2.2700x; 1.0525x over previous
#include <cuda_runtime.h>
#include <cuda_bf16.h>
#include <cstdint>

#define N_NODE  256
#define IN_DIM  256
#define LAT     8192
#define OUT_DIM 2048
#define KSPLIT  4

// ---------------- device scratch (no allocations allowed) -------------------
__device__ __nv_bfloat16 g_ahi[N_NODE * LAT];      // 4 MB  A hi  [m][k]
__device__ __nv_bfloat16 g_alo[N_NODE * LAT];      // 4 MB  A lo  [m][k]
__device__ __nv_bfloat16 g_bhi2[LAT * OUT_DIM];    // 32 MB W2 hi [k][n] (native)
__device__ __nv_bfloat16 g_blo2[LAT * OUT_DIM];    // 32 MB W2 lo [k][n]
__device__ float g_part[KSPLIT][N_NODE * OUT_DIM]; // 8 MB  GEMM2 K-split partials
__device__ float g_p0[N_NODE * OUT_DIM];           // 2 MB  exp(keys0/2)

// ---------------- helpers (sm_80-level PTX only) ----------------------------
__device__ __forceinline__ uint32_t smem_u32(const void* p) {
    uint32_t a;
    asm("{ .reg .u64 t; cvta.to.shared.u64 t, %1; cvt.u32.u64 %0, t; }" : "=r"(a) : "l"(p));
    return a;
}
__device__ __forceinline__ void cpa16(uint32_t s, const void* g) {
    asm volatile("cp.async.cg.shared.global [%0], [%1], 16;" :: "r"(s), "l"(g));
}
#define CP_COMMIT()  asm volatile("cp.async.commit_group;" ::: "memory")
#define CP_WAIT(n)   asm volatile("cp.async.wait_group %0;" :: "n"(n) : "memory")

__device__ __forceinline__ void mma_bf16(float* c, const uint32_t* a, const uint32_t* b) {
    asm volatile(
        "mma.sync.aligned.m16n8k16.row.col.f32.bf16.bf16.f32 "
        "{%0,%1,%2,%3}, {%4,%5,%6,%7}, {%8,%9}, {%0,%1,%2,%3};"
        : "+f"(c[0]), "+f"(c[1]), "+f"(c[2]), "+f"(c[3])
        : "r"(a[0]), "r"(a[1]), "r"(a[2]), "r"(a[3]), "r"(b[0]), "r"(b[1]));
}
__device__ __forceinline__ void ldsm4(uint32_t& r0, uint32_t& r1, uint32_t& r2, uint32_t& r3, uint32_t a) {
    asm volatile("ldmatrix.sync.aligned.m8n8.x4.shared.b16 {%0,%1,%2,%3}, [%4];"
                 : "=r"(r0), "=r"(r1), "=r"(r2), "=r"(r3) : "r"(a));
}
__device__ __forceinline__ void ldsm4t(uint32_t& r0, uint32_t& r1, uint32_t& r2, uint32_t& r3, uint32_t a) {
    asm volatile("ldmatrix.sync.aligned.m8n8.x4.trans.shared.b16 {%0,%1,%2,%3}, [%4];"
                 : "=r"(r0), "=r"(r1), "=r"(r2), "=r"(r3) : "r"(a));
}

// ---------------------------------------------------------------------------
// GEMM1 (SIMT fp32): A = relu(adj @ W1 + b1) -> bf16 hi/lo split ([m][k])
// ---------------------------------------------------------------------------
__global__ void __launch_bounds__(256)
gemm1_kernel(const float* __restrict__ A,
             const float* __restrict__ B,
             const float* __restrict__ bias)
{
    __shared__ float As[2][16][64];
    __shared__ float Bs[2][16][64];
    const int tid = threadIdx.x;
    const int bm  = blockIdx.y * 64;
    const int bn  = blockIdx.x * 64;

    const int arow = tid >> 2, acol = (tid & 3) << 2;
    const int brow = tid >> 4, bcol = (tid & 15) << 2;

    const float* Aptr = A + (size_t)(bm + arow) * IN_DIM + acol;
    const float* Bptr = B + (size_t)brow * LAT + bn + bcol;

    float4 aReg = *(const float4*)Aptr;
    float4 bReg = *(const float4*)Bptr;
    As[0][acol+0][arow] = aReg.x; As[0][acol+1][arow] = aReg.y;
    As[0][acol+2][arow] = aReg.z; As[0][acol+3][arow] = aReg.w;
    *(float4*)&Bs[0][brow][bcol] = bReg;
    __syncthreads();

    float acc[4][4];
#pragma unroll
    for (int i = 0; i < 4; i++)
#pragma unroll
        for (int j = 0; j < 4; j++) acc[i][j] = 0.f;

    const int tx = tid & 15, ty = tid >> 4;
    const int nT = IN_DIM / 16;
    for (int t = 0; t < nT; ++t) {
        const int cur = t & 1;
        if (t + 1 < nT) {
            aReg = *(const float4*)(Aptr + (t + 1) * 16);
            bReg = *(const float4*)(Bptr + (size_t)(t + 1) * 16 * LAT);
        }
#pragma unroll
        for (int k = 0; k < 16; ++k) {
            float ar[4], br[4];
            *(float4*)ar = *(const float4*)&As[cur][k][ty << 2];
            *(float4*)br = *(const float4*)&Bs[cur][k][tx << 2];
#pragma unroll
            for (int i = 0; i < 4; i++)
#pragma unroll
                for (int j = 0; j < 4; j++) acc[i][j] += ar[i] * br[j];
        }
        if (t + 1 < nT) {
            const int nxt = cur ^ 1;
            As[nxt][acol+0][arow] = aReg.x; As[nxt][acol+1][arow] = aReg.y;
            As[nxt][acol+2][arow] = aReg.z; As[nxt][acol+3][arow] = aReg.w;
            *(float4*)&Bs[nxt][brow][bcol] = bReg;
        }
        __syncthreads();
    }

    float4 bv = *(const float4*)&bias[bn + (tx << 2)];
#pragma unroll
    for (int i = 0; i < 4; i++) {
        const int row = bm + (ty << 2) + i;
        float v[4];
        v[0] = fmaxf(acc[i][0] + bv.x, 0.f);
        v[1] = fmaxf(acc[i][1] + bv.y, 0.f);
        v[2] = fmaxf(acc[i][2] + bv.z, 0.f);
        v[3] = fmaxf(acc[i][3] + bv.w, 0.f);
        const size_t base = (size_t)row * LAT + bn + (tx << 2);
#pragma unroll
        for (int j = 0; j < 4; j += 2) {
            __nv_bfloat16 h0 = __float2bfloat16_rn(v[j]);
            __nv_bfloat16 h1 = __float2bfloat16_rn(v[j+1]);
            __nv_bfloat16 l0 = __float2bfloat16_rn(v[j]   - __bfloat162float(h0));
            __nv_bfloat16 l1 = __float2bfloat16_rn(v[j+1] - __bfloat162float(h1));
            __nv_bfloat162 h; h.x = h0; h.y = h1;
            __nv_bfloat162 l; l.x = l0; l.y = l1;
            *(__nv_bfloat162*)(g_ahi + base + j) = h;
            *(__nv_bfloat162*)(g_alo + base + j) = l;
        }
    }
}

// ---------------------------------------------------------------------------
// W2 [k][n] fp32 -> bf16 hi/lo, layout preserved. Pure streaming.
// 16.78M elems as 4.19M float4 -> grid 16384 x 256
// ---------------------------------------------------------------------------
__global__ void __launch_bounds__(256)
w2conv_kernel(const float* __restrict__ W2)
{
    const int i = blockIdx.x * 256 + threadIdx.x;   // float4 index
    const float4 v = ((const float4*)W2)[i];
    __nv_bfloat16 h0 = __float2bfloat16_rn(v.x);
    __nv_bfloat16 h1 = __float2bfloat16_rn(v.y);
    __nv_bfloat16 h2 = __float2bfloat16_rn(v.z);
    __nv_bfloat16 h3 = __float2bfloat16_rn(v.w);
    __nv_bfloat162 hA; hA.x = h0; hA.y = h1;
    __nv_bfloat162 hB; hB.x = h2; hB.y = h3;
    __nv_bfloat162 lA; lA.x = __float2bfloat16_rn(v.x - __bfloat162float(h0));
                       lA.y = __float2bfloat16_rn(v.y - __bfloat162float(h1));
    __nv_bfloat162 lB; lB.x = __float2bfloat16_rn(v.z - __bfloat162float(h2));
                       lB.y = __float2bfloat16_rn(v.w - __bfloat162float(h3));
    *(__nv_bfloat162*)(g_bhi2 + i * 4)     = hA;
    *(__nv_bfloat162*)(g_bhi2 + i * 4 + 2) = hB;
    *(__nv_bfloat162*)(g_blo2 + i * 4)     = lA;
    *(__nv_bfloat162*)(g_blo2 + i * 4 + 2) = lB;
}

// ---------------------------------------------------------------------------
// GEMM2 via mma.sync bf16 split + ldmatrix: g_part[z] = A @ W2 slice
// CTA tile 128x128, BK=32, 4-stage cp.async ring, 8 warps (2x4 of 64x32).
// A smem [m=128][k=32] rows padded to 80B (conflict-free ldmatrix).
// B smem [k=32][n=128] rows padded to 272B (conflict-free ldmatrix.trans).
// 3-term split: Ahi*Bhi + Ahi*Blo + Alo*Bhi.
// ---------------------------------------------------------------------------
#define BM 128
#define BN 128
#define BK 32
#define KPER   (LAT / KSPLIT)   // 2048
#define NSTAGE (KPER / BK)      // 64
#define AROWB  80               // A row bytes (64 data + 16 pad)
#define BROWB  272              // B row bytes (256 data + 16 pad)
#define OFF_AL 10240            // 128*80
#define OFF_BH 20480
#define OFF_BL 29184            // 20480 + 32*272
#define STG    37888            // stage bytes
#define NST    4
#define G2_SMEM (NST * STG)     // 151552

__global__ void __launch_bounds__(256)
gemm2_mma_kernel()
{
    extern __shared__ uint8_t smraw[];
    const uint32_t sbase = smem_u32(smraw);
    const int tid  = threadIdx.x;
    const int wid  = tid >> 5, lane = tid & 31;
    const int g    = lane >> 2, t = lane & 3;
    const int bn   = blockIdx.x * BN;
    const int bm   = blockIdx.y * BM;
    const int kz   = blockIdx.z * KPER;
    const int wm   = (wid >> 2) * 64;   // 0 or 64
    const int wn   = (wid & 3) * 32;    // 0,32,64,96
    const int l15  = lane & 15;
    const int l16  = (lane >> 4) & 1;

    float acc[4][4][4];
#pragma unroll
    for (int i = 0; i < 4; i++)
#pragma unroll
        for (int j = 0; j < 4; j++)
#pragma unroll
            for (int r = 0; r < 4; r++) acc[i][j][r] = 0.f;

    // ---- loader: 8 x cp.async(16B) per thread per stage ----
    auto load_stage = [&](int s) {
        const int kb = kz + s * BK;
        const uint32_t sb = sbase + (uint32_t)(s & (NST - 1)) * STG;
        // A: 512 chunks of 16B per operand (128 rows x 4 chunks)
#pragma unroll
        for (int j = 0; j < 2; j++) {
            const int c = j * 256 + tid;
            const int row = c >> 2, ch = c & 3;
            const uint32_t off = (uint32_t)(row * AROWB + ch * 16);
            const size_t gA = (size_t)(bm + row) * LAT + kb + ch * 8;
            cpa16(sb + off,          g_ahi + gA);
            cpa16(sb + OFF_AL + off, g_alo + gA);
        }
        // B: 512 chunks of 16B per operand (32 rows x 16 chunks)
#pragma unroll
        for (int j = 0; j < 2; j++) {
            const int c = j * 256 + tid;
            const int row = c >> 4, ch = c & 15;
            const uint32_t off = (uint32_t)(row * BROWB + ch * 16);
            const size_t gB = (size_t)(kb + row) * OUT_DIM + bn + ch * 8;
            cpa16(sb + OFF_BH + off, g_bhi2 + gB);
            cpa16(sb + OFF_BL + off, g_blo2 + gB);
        }
    };

    load_stage(0); CP_COMMIT();
    load_stage(1); CP_COMMIT();
    load_stage(2); CP_COMMIT();

#pragma unroll 1
    for (int s = 0; s < NSTAGE; ++s) {
        if (s + 2 < NSTAGE)      { CP_WAIT(2); }
        else if (s + 1 < NSTAGE) { CP_WAIT(1); }
        else                     { CP_WAIT(0); }
        __syncthreads();
        if (s + 3 < NSTAGE) { load_stage(s + 3); CP_COMMIT(); }

        const uint32_t sb = sbase + (uint32_t)(s & (NST - 1)) * STG;
#pragma unroll
        for (int ks = 0; ks < 2; ++ks) {
            // B fragments: ldmatrix.x4.trans, 2 j-pairs, hi & lo
            uint32_t bh[4][2], bl[4][2];
#pragma unroll
            for (int jp = 0; jp < 2; jp++) {
                const uint32_t ba = sb + OFF_BH
                    + (uint32_t)((ks * 16 + l15) * BROWB)
                    + (uint32_t)((wn + jp * 16 + l16 * 8) * 2);
                ldsm4t(bh[2*jp][0], bh[2*jp][1], bh[2*jp+1][0], bh[2*jp+1][1], ba);
                ldsm4t(bl[2*jp][0], bl[2*jp][1], bl[2*jp+1][0], bl[2*jp+1][1],
                       ba + (OFF_BL - OFF_BH));
            }
#pragma unroll
            for (int i = 0; i < 4; i++) {
                const uint32_t aa = sb
                    + (uint32_t)((wm + i * 16 + l15) * AROWB)
                    + (uint32_t)(ks * 32 + l16 * 16);
                uint32_t ah[4], al[4];
                ldsm4(ah[0], ah[1], ah[2], ah[3], aa);
                ldsm4(al[0], al[1], al[2], al[3], aa + OFF_AL);
#pragma unroll
                for (int j = 0; j < 4; j++) {
                    mma_bf16(acc[i][j], ah, bh[j]);
                    mma_bf16(acc[i][j], ah, bl[j]);
                    mma_bf16(acc[i][j], al, bh[j]);
                }
            }
        }
    }

    // ---- epilogue: write fp32 partial tile ----
    float* P = g_part[blockIdx.z];
#pragma unroll
    for (int i = 0; i < 4; i++) {
#pragma unroll
        for (int j = 0; j < 4; j++) {
            const int row0 = bm + wm + i * 16 + g;
            const int col  = bn + wn + j * 8 + t * 2;
            float2 v0; v0.x = acc[i][j][0]; v0.y = acc[i][j][1];
            float2 v1; v1.x = acc[i][j][2]; v1.y = acc[i][j][3];
            *(float2*)(P + (size_t)row0 * OUT_DIM + col)       = v0;
            *(float2*)(P + (size_t)(row0 + 8) * OUT_DIM + col) = v1;
        }
    }
}

// ---------------------------------------------------------------------------
// p0 = sqrt(relu(sum_partials + b2) + 1e-30) * exp(z/2)
// ---------------------------------------------------------------------------
__global__ void __launch_bounds__(256)
p0_kernel(const float* __restrict__ b2, const float* __restrict__ Z)
{
    const int idx = blockIdx.x * 256 + threadIdx.x;     // float4 index
    float4 s = ((const float4*)g_part[0])[idx];
#pragma unroll
    for (int k = 1; k < KSPLIT; k++) {
        float4 t = ((const float4*)g_part[k])[idx];
        s.x += t.x; s.y += t.y; s.z += t.z; s.w += t.w;
    }
    const float4 bv = ((const float4*)b2)[idx & 511];
    const float4 zv = ((const float4*)Z)[idx];
    float4 o;
    o.x = sqrtf(fmaxf(s.x + bv.x, 0.f) + 1e-30f) * __expf(0.5f * zv.x);
    o.y = sqrtf(fmaxf(s.y + bv.y, 0.f) + 1e-30f) * __expf(0.5f * zv.y);
    o.z = sqrtf(fmaxf(s.z + bv.z, 0.f) + 1e-30f) * __expf(0.5f * zv.z);
    o.w = sqrtf(fmaxf(s.w + bv.w, 0.f) + 1e-30f) * __expf(0.5f * zv.w);
    ((float4*)g_p0)[idx] = o;
}

// ---------------------------------------------------------------------------
// Relaxed top-k in p-space (t=2). sqrt(1-y) via 4-term poly for y<=1/16,
// exact sqrtf fallback for rare big-y lanes.
// ---------------------------------------------------------------------------
__global__ void __launch_bounds__(256)
topm_kernel(float* __restrict__ out)
{
    const int row = blockIdx.x;
    const int tid = threadIdx.x;
    const float4* pr = (const float4*)(g_p0 + (size_t)row * OUT_DIM);

    float p[8], one[8], kh[8];
    {
        float4 v0 = pr[tid * 2];
        float4 v1 = pr[tid * 2 + 1];
        p[0]=v0.x; p[1]=v0.y; p[2]=v0.z; p[3]=v0.w;
        p[4]=v1.x; p[5]=v1.y; p[6]=v1.z; p[7]=v1.w;
    }
#pragma unroll
    for (int j = 0; j < 8; j++) { one[j] = 0.f; kh[j] = 0.f; }

    __shared__ float wsum[2][8];

    for (int it = 0; it < N_NODE; ++it) {
        float sc[8];
        bool any = false;
#pragma unroll
        for (int j = 0; j < 8; j++) {
            const float y = one[j];
            sc[j] = 1.f - y * (0.5f + y * (0.125f + y * (0.0625f + y * 0.0390625f)));
            any = any || (y > 0.0625f);
        }
        if (__ballot_sync(0xffffffffu, any)) {
#pragma unroll
            for (int j = 0; j < 8; j++)
                if (one[j] > 0.0625f) sc[j] = sqrtf(fmaxf(1.f - one[j], 1e-20f));
        }
#pragma unroll
        for (int j = 0; j < 8; j++) p[j] *= sc[j];

        float loc = ((p[0] + p[1]) + (p[2] + p[3])) + ((p[4] + p[5]) + (p[6] + p[7]));
#pragma unroll
        for (int off = 16; off > 0; off >>= 1)
            loc += __shfl_xor_sync(0xffffffffu, loc, off);

        const int buf = it & 1;
        if ((tid & 31) == 0) wsum[buf][tid >> 5] = loc;
        __syncthreads();

        float4 a = *(float4*)&wsum[buf][0];
        float4 b = *(float4*)&wsum[buf][4];
        const float s = ((a.x + a.y) + (a.z + a.w)) + ((b.x + b.y) + (b.z + b.w));
        const float inv = __fdividef(1.0f, s);

#pragma unroll
        for (int j = 0; j < 8; j++) {
            one[j] = p[j] * inv;
            kh[j] += one[j];
        }
    }

    float4* orow = (float4*)(out + (size_t)row * OUT_DIM);
    orow[tid * 2]     = make_float4(kh[0], kh[1], kh[2], kh[3]);
    orow[tid * 2 + 1] = make_float4(kh[4], kh[5], kh[6], kh[7]);
}

// ---------------------------------------------------------------------------
extern "C" void kernel_launch(void* const* d_in, const int* in_sizes, int n_in,
                              void* d_out, int out_size)
{
    const float* adj = (const float*)d_in[0];
    const float* W1  = (const float*)d_in[1];
    const float* b1  = (const float*)d_in[2];
    const float* W2  = (const float*)d_in[3];
    const float* b2  = (const float*)d_in[4];
    const float* z   = (const float*)d_in[5];
    float* out = (float*)d_out;

    cudaFuncSetAttribute(gemm2_mma_kernel,
                         cudaFuncAttributeMaxDynamicSharedMemorySize, G2_SMEM);

    // W2 -> bf16 hi/lo (layout preserved, streaming)
    w2conv_kernel<<<(LAT * OUT_DIM / 4) / 256, 256>>>(W2);

    // Layer 1: A = relu(adj @ W1 + b1) -> bf16 hi/lo
    gemm1_kernel<<<dim3(LAT / 64, N_NODE / 64), 256>>>(adj, W1, b1);

    // Layer 2: mma.sync split-bf16 + ldmatrix, K-split partials
    gemm2_mma_kernel<<<dim3(OUT_DIM / BN, N_NODE / BM, KSPLIT), 256, G2_SMEM>>>();

    // p0
    p0_kernel<<<512, 256>>>(b2, z);

    // top-m
    topm_kernel<<<N_NODE, 256>>>(out);
}

// round 9
// speedup vs baseline: 2.2703x; 1.0001x over previous
#include <cuda_runtime.h>
#include <cuda_bf16.h>
#include <cstdint>

#define N_NODE  256
#define IN_DIM  256
#define LAT     8192
#define OUT_DIM 2048
#define KSPLIT  4

// ---------------- device scratch (no allocations allowed) -------------------
__device__ __nv_bfloat16 g_ahi[N_NODE * LAT];      // 4 MB  A hi  [m][k]
__device__ __nv_bfloat16 g_alo[N_NODE * LAT];      // 4 MB  A lo  [m][k]
__device__ __nv_bfloat16 g_bhi2[LAT * OUT_DIM];    // 32 MB W2 hi [k][n] (native)
__device__ __nv_bfloat16 g_blo2[LAT * OUT_DIM];    // 32 MB W2 lo [k][n]
__device__ float g_part[KSPLIT][N_NODE * OUT_DIM]; // 8 MB  GEMM2 K-split partials
__device__ float g_p0[N_NODE * OUT_DIM];           // 2 MB  exp(keys0/2)

// ---------------- helpers (sm_80-level PTX only) ----------------------------
__device__ __forceinline__ uint32_t smem_u32(const void* p) {
    uint32_t a;
    asm("{ .reg .u64 t; cvta.to.shared.u64 t, %1; cvt.u32.u64 %0, t; }" : "=r"(a) : "l"(p));
    return a;
}
__device__ __forceinline__ void cpa16(uint32_t s, const void* g) {
    asm volatile("cp.async.cg.shared.global [%0], [%1], 16;" :: "r"(s), "l"(g));
}
#define CP_COMMIT()  asm volatile("cp.async.commit_group;" ::: "memory")
#define CP_WAIT(n)   asm volatile("cp.async.wait_group %0;" :: "n"(n) : "memory")

__device__ __forceinline__ void mma_bf16(float* c, const uint32_t* a, const uint32_t* b) {
    asm volatile(
        "mma.sync.aligned.m16n8k16.row.col.f32.bf16.bf16.f32 "
        "{%0,%1,%2,%3}, {%4,%5,%6,%7}, {%8,%9}, {%0,%1,%2,%3};"
        : "+f"(c[0]), "+f"(c[1]), "+f"(c[2]), "+f"(c[3])
        : "r"(a[0]), "r"(a[1]), "r"(a[2]), "r"(a[3]), "r"(b[0]), "r"(b[1]));
}
__device__ __forceinline__ void ldsm4(uint32_t& r0, uint32_t& r1, uint32_t& r2, uint32_t& r3, uint32_t a) {
    asm volatile("ldmatrix.sync.aligned.m8n8.x4.shared.b16 {%0,%1,%2,%3}, [%4];"
                 : "=r"(r0), "=r"(r1), "=r"(r2), "=r"(r3) : "r"(a));
}
__device__ __forceinline__ void ldsm4t(uint32_t& r0, uint32_t& r1, uint32_t& r2, uint32_t& r3, uint32_t a) {
    asm volatile("ldmatrix.sync.aligned.m8n8.x4.trans.shared.b16 {%0,%1,%2,%3}, [%4];"
                 : "=r"(r0), "=r"(r1), "=r"(r2), "=r"(r3) : "r"(a));
}

// ---------------------------------------------------------------------------
// GEMM1 (SIMT fp32): A = relu(adj @ W1 + b1) -> bf16 hi/lo split ([m][k])
// ---------------------------------------------------------------------------
__global__ void __launch_bounds__(256)
gemm1_kernel(const float* __restrict__ A,
             const float* __restrict__ B,
             const float* __restrict__ bias)
{
    __shared__ float As[2][16][64];
    __shared__ float Bs[2][16][64];
    const int tid = threadIdx.x;
    const int bm  = blockIdx.y * 64;
    const int bn  = blockIdx.x * 64;

    const int arow = tid >> 2, acol = (tid & 3) << 2;
    const int brow = tid >> 4, bcol = (tid & 15) << 2;

    const float* Aptr = A + (size_t)(bm + arow) * IN_DIM + acol;
    const float* Bptr = B + (size_t)brow * LAT + bn + bcol;

    float4 aReg = *(const float4*)Aptr;
    float4 bReg = *(const float4*)Bptr;
    As[0][acol+0][arow] = aReg.x; As[0][acol+1][arow] = aReg.y;
    As[0][acol+2][arow] = aReg.z; As[0][acol+3][arow] = aReg.w;
    *(float4*)&Bs[0][brow][bcol] = bReg;
    __syncthreads();

    float acc[4][4];
#pragma unroll
    for (int i = 0; i < 4; i++)
#pragma unroll
        for (int j = 0; j < 4; j++) acc[i][j] = 0.f;

    const int tx = tid & 15, ty = tid >> 4;
    const int nT = IN_DIM / 16;
    for (int t = 0; t < nT; ++t) {
        const int cur = t & 1;
        if (t + 1 < nT) {
            aReg = *(const float4*)(Aptr + (t + 1) * 16);
            bReg = *(const float4*)(Bptr + (size_t)(t + 1) * 16 * LAT);
        }
#pragma unroll
        for (int k = 0; k < 16; ++k) {
            float ar[4], br[4];
            *(float4*)ar = *(const float4*)&As[cur][k][ty << 2];
            *(float4*)br = *(const float4*)&Bs[cur][k][tx << 2];
#pragma unroll
            for (int i = 0; i < 4; i++)
#pragma unroll
                for (int j = 0; j < 4; j++) acc[i][j] += ar[i] * br[j];
        }
        if (t + 1 < nT) {
            const int nxt = cur ^ 1;
            As[nxt][acol+0][arow] = aReg.x; As[nxt][acol+1][arow] = aReg.y;
            As[nxt][acol+2][arow] = aReg.z; As[nxt][acol+3][arow] = aReg.w;
            *(float4*)&Bs[nxt][brow][bcol] = bReg;
        }
        __syncthreads();
    }

    float4 bv = *(const float4*)&bias[bn + (tx << 2)];
#pragma unroll
    for (int i = 0; i < 4; i++) {
        const int row = bm + (ty << 2) + i;
        float v[4];
        v[0] = fmaxf(acc[i][0] + bv.x, 0.f);
        v[1] = fmaxf(acc[i][1] + bv.y, 0.f);
        v[2] = fmaxf(acc[i][2] + bv.z, 0.f);
        v[3] = fmaxf(acc[i][3] + bv.w, 0.f);
        const size_t base = (size_t)row * LAT + bn + (tx << 2);
#pragma unroll
        for (int j = 0; j < 4; j += 2) {
            __nv_bfloat16 h0 = __float2bfloat16_rn(v[j]);
            __nv_bfloat16 h1 = __float2bfloat16_rn(v[j+1]);
            __nv_bfloat16 l0 = __float2bfloat16_rn(v[j]   - __bfloat162float(h0));
            __nv_bfloat16 l1 = __float2bfloat16_rn(v[j+1] - __bfloat162float(h1));
            __nv_bfloat162 h; h.x = h0; h.y = h1;
            __nv_bfloat162 l; l.x = l0; l.y = l1;
            *(__nv_bfloat162*)(g_ahi + base + j) = h;
            *(__nv_bfloat162*)(g_alo + base + j) = l;
        }
    }
}

// ---------------------------------------------------------------------------
// W2 [k][n] fp32 -> bf16 hi/lo, layout preserved. Pure streaming.
// 16.78M elems as 4.19M float4 -> grid 16384 x 256
// ---------------------------------------------------------------------------
__global__ void __launch_bounds__(256)
w2conv_kernel(const float* __restrict__ W2)
{
    const int i = blockIdx.x * 256 + threadIdx.x;   // float4 index
    const float4 v = ((const float4*)W2)[i];
    __nv_bfloat16 h0 = __float2bfloat16_rn(v.x);
    __nv_bfloat16 h1 = __float2bfloat16_rn(v.y);
    __nv_bfloat16 h2 = __float2bfloat16_rn(v.z);
    __nv_bfloat16 h3 = __float2bfloat16_rn(v.w);
    __nv_bfloat162 hA; hA.x = h0; hA.y = h1;
    __nv_bfloat162 hB; hB.x = h2; hB.y = h3;
    __nv_bfloat162 lA; lA.x = __float2bfloat16_rn(v.x - __bfloat162float(h0));
                       lA.y = __float2bfloat16_rn(v.y - __bfloat162float(h1));
    __nv_bfloat162 lB; lB.x = __float2bfloat16_rn(v.z - __bfloat162float(h2));
                       lB.y = __float2bfloat16_rn(v.w - __bfloat162float(h3));
    *(__nv_bfloat162*)(g_bhi2 + i * 4)     = hA;
    *(__nv_bfloat162*)(g_bhi2 + i * 4 + 2) = hB;
    *(__nv_bfloat162*)(g_blo2 + i * 4)     = lA;
    *(__nv_bfloat162*)(g_blo2 + i * 4 + 2) = lB;
}

// ---------------------------------------------------------------------------
// GEMM2 via mma.sync bf16 split + ldmatrix: g_part[z] = A @ W2 slice
// CTA tile 128x128, BK=32, 4-stage cp.async ring, 8 warps (2x4 of 64x32).
// A smem [m=128][k=32] rows padded to 80B (conflict-free ldmatrix).
// B smem [k=32][n=128] rows padded to 272B (conflict-free ldmatrix.trans).
// 3-term split: Ahi*Bhi + Ahi*Blo + Alo*Bhi.
// ---------------------------------------------------------------------------
#define BM 128
#define BN 128
#define BK 32
#define KPER   (LAT / KSPLIT)   // 2048
#define NSTAGE (KPER / BK)      // 64
#define AROWB  80               // A row bytes (64 data + 16 pad)
#define BROWB  272              // B row bytes (256 data + 16 pad)
#define OFF_AL 10240            // 128*80
#define OFF_BH 20480
#define OFF_BL 29184            // 20480 + 32*272
#define STG    37888            // stage bytes
#define NST    4
#define G2_SMEM (NST * STG)     // 151552

__global__ void __launch_bounds__(256)
gemm2_mma_kernel()
{
    extern __shared__ uint8_t smraw[];
    const uint32_t sbase = smem_u32(smraw);
    const int tid  = threadIdx.x;
    const int wid  = tid >> 5, lane = tid & 31;
    const int g    = lane >> 2, t = lane & 3;
    const int bn   = blockIdx.x * BN;
    const int bm   = blockIdx.y * BM;
    const int kz   = blockIdx.z * KPER;
    const int wm   = (wid >> 2) * 64;   // 0 or 64
    const int wn   = (wid & 3) * 32;    // 0,32,64,96
    const int l15  = lane & 15;
    const int l16  = (lane >> 4) & 1;

    float acc[4][4][4];
#pragma unroll
    for (int i = 0; i < 4; i++)
#pragma unroll
        for (int j = 0; j < 4; j++)
#pragma unroll
            for (int r = 0; r < 4; r++) acc[i][j][r] = 0.f;

    // ---- loader: 8 x cp.async(16B) per thread per stage ----
    auto load_stage = [&](int s) {
        const int kb = kz + s * BK;
        const uint32_t sb = sbase + (uint32_t)(s & (NST - 1)) * STG;
        // A: 512 chunks of 16B per operand (128 rows x 4 chunks)
#pragma unroll
        for (int j = 0; j < 2; j++) {
            const int c = j * 256 + tid;
            const int row = c >> 2, ch = c & 3;
            const uint32_t off = (uint32_t)(row * AROWB + ch * 16);
            const size_t gA = (size_t)(bm + row) * LAT + kb + ch * 8;
            cpa16(sb + off,          g_ahi + gA);
            cpa16(sb + OFF_AL + off, g_alo + gA);
        }
        // B: 512 chunks of 16B per operand (32 rows x 16 chunks)
#pragma unroll
        for (int j = 0; j < 2; j++) {
            const int c = j * 256 + tid;
            const int row = c >> 4, ch = c & 15;
            const uint32_t off = (uint32_t)(row * BROWB + ch * 16);
            const size_t gB = (size_t)(kb + row) * OUT_DIM + bn + ch * 8;
            cpa16(sb + OFF_BH + off, g_bhi2 + gB);
            cpa16(sb + OFF_BL + off, g_blo2 + gB);
        }
    };

    load_stage(0); CP_COMMIT();
    load_stage(1); CP_COMMIT();
    load_stage(2); CP_COMMIT();

#pragma unroll 1
    for (int s = 0; s < NSTAGE; ++s) {
        if (s + 2 < NSTAGE)      { CP_WAIT(2); }
        else if (s + 1 < NSTAGE) { CP_WAIT(1); }
        else                     { CP_WAIT(0); }
        __syncthreads();
        if (s + 3 < NSTAGE) { load_stage(s + 3); CP_COMMIT(); }

        const uint32_t sb = sbase + (uint32_t)(s & (NST - 1)) * STG;
#pragma unroll
        for (int ks = 0; ks < 2; ++ks) {
            // B fragments: ldmatrix.x4.trans, 2 j-pairs, hi & lo
            uint32_t bh[4][2], bl[4][2];
#pragma unroll
            for (int jp = 0; jp < 2; jp++) {
                const uint32_t ba = sb + OFF_BH
                    + (uint32_t)((ks * 16 + l15) * BROWB)
                    + (uint32_t)((wn + jp * 16 + l16 * 8) * 2);
                ldsm4t(bh[2*jp][0], bh[2*jp][1], bh[2*jp+1][0], bh[2*jp+1][1], ba);
                ldsm4t(bl[2*jp][0], bl[2*jp][1], bl[2*jp+1][0], bl[2*jp+1][1],
                       ba + (OFF_BL - OFF_BH));
            }
#pragma unroll
            for (int i = 0; i < 4; i++) {
                const uint32_t aa = sb
                    + (uint32_t)((wm + i * 16 + l15) * AROWB)
                    + (uint32_t)(ks * 32 + l16 * 16);
                uint32_t ah[4], al[4];
                ldsm4(ah[0], ah[1], ah[2], ah[3], aa);
                ldsm4(al[0], al[1], al[2], al[3], aa + OFF_AL);
#pragma unroll
                for (int j = 0; j < 4; j++) {
                    mma_bf16(acc[i][j], ah, bh[j]);
                    mma_bf16(acc[i][j], ah, bl[j]);
                    mma_bf16(acc[i][j], al, bh[j]);
                }
            }
        }
    }

    // ---- epilogue: write fp32 partial tile ----
    float* P = g_part[blockIdx.z];
#pragma unroll
    for (int i = 0; i < 4; i++) {
#pragma unroll
        for (int j = 0; j < 4; j++) {
            const int row0 = bm + wm + i * 16 + g;
            const int col  = bn + wn + j * 8 + t * 2;
            float2 v0; v0.x = acc[i][j][0]; v0.y = acc[i][j][1];
            float2 v1; v1.x = acc[i][j][2]; v1.y = acc[i][j][3];
            *(float2*)(P + (size_t)row0 * OUT_DIM + col)       = v0;
            *(float2*)(P + (size_t)(row0 + 8) * OUT_DIM + col) = v1;
        }
    }
}

// ---------------------------------------------------------------------------
// p0 = sqrt(relu(sum_partials + b2) + 1e-30) * exp(z/2)
// ---------------------------------------------------------------------------
__global__ void __launch_bounds__(256)
p0_kernel(const float* __restrict__ b2, const float* __restrict__ Z)
{
    const int idx = blockIdx.x * 256 + threadIdx.x;     // float4 index
    float4 s = ((const float4*)g_part[0])[idx];
#pragma unroll
    for (int k = 1; k < KSPLIT; k++) {
        float4 t = ((const float4*)g_part[k])[idx];
        s.x += t.x; s.y += t.y; s.z += t.z; s.w += t.w;
    }
    const float4 bv = ((const float4*)b2)[idx & 511];
    const float4 zv = ((const float4*)Z)[idx];
    float4 o;
    o.x = sqrtf(fmaxf(s.x + bv.x, 0.f) + 1e-30f) * __expf(0.5f * zv.x);
    o.y = sqrtf(fmaxf(s.y + bv.y, 0.f) + 1e-30f) * __expf(0.5f * zv.y);
    o.z = sqrtf(fmaxf(s.z + bv.z, 0.f) + 1e-30f) * __expf(0.5f * zv.z);
    o.w = sqrtf(fmaxf(s.w + bv.w, 0.f) + 1e-30f) * __expf(0.5f * zv.w);
    ((float4*)g_p0)[idx] = o;
}

// ---------------------------------------------------------------------------
// Relaxed top-k in p-space (t=2). sqrt(1-y) via 4-term poly for y<=1/16,
// exact sqrtf fallback for rare big-y lanes.
// ---------------------------------------------------------------------------
__global__ void __launch_bounds__(256)
topm_kernel(float* __restrict__ out)
{
    const int row = blockIdx.x;
    const int tid = threadIdx.x;
    const float4* pr = (const float4*)(g_p0 + (size_t)row * OUT_DIM);

    float p[8], one[8], kh[8];
    {
        float4 v0 = pr[tid * 2];
        float4 v1 = pr[tid * 2 + 1];
        p[0]=v0.x; p[1]=v0.y; p[2]=v0.z; p[3]=v0.w;
        p[4]=v1.x; p[5]=v1.y; p[6]=v1.z; p[7]=v1.w;
    }
#pragma unroll
    for (int j = 0; j < 8; j++) { one[j] = 0.f; kh[j] = 0.f; }

    __shared__ float wsum[2][8];

    for (int it = 0; it < N_NODE; ++it) {
        float sc[8];
        bool any = false;
#pragma unroll
        for (int j = 0; j < 8; j++) {
            const float y = one[j];
            sc[j] = 1.f - y * (0.5f + y * (0.125f + y * (0.0625f + y * 0.0390625f)));
            any = any || (y > 0.0625f);
        }
        if (__ballot_sync(0xffffffffu, any)) {
#pragma unroll
            for (int j = 0; j < 8; j++)
                if (one[j] > 0.0625f) sc[j] = sqrtf(fmaxf(1.f - one[j], 1e-20f));
        }
#pragma unroll
        for (int j = 0; j < 8; j++) p[j] *= sc[j];

        float loc = ((p[0] + p[1]) + (p[2] + p[3])) + ((p[4] + p[5]) + (p[6] + p[7]));
#pragma unroll
        for (int off = 16; off > 0; off >>= 1)
            loc += __shfl_xor_sync(0xffffffffu, loc, off);

        const int buf = it & 1;
        if ((tid & 31) == 0) wsum[buf][tid >> 5] = loc;
        __syncthreads();

        float4 a = *(float4*)&wsum[buf][0];
        float4 b = *(float4*)&wsum[buf][4];
        const float s = ((a.x + a.y) + (a.z + a.w)) + ((b.x + b.y) + (b.z + b.w));
        const float inv = __fdividef(1.0f, s);

#pragma unroll
        for (int j = 0; j < 8; j++) {
            one[j] = p[j] * inv;
            kh[j] += one[j];
        }
    }

    float4* orow = (float4*)(out + (size_t)row * OUT_DIM);
    orow[tid * 2]     = make_float4(kh[0], kh[1], kh[2], kh[3]);
    orow[tid * 2 + 1] = make_float4(kh[4], kh[5], kh[6], kh[7]);
}

// ---------------------------------------------------------------------------
extern "C" void kernel_launch(void* const* d_in, const int* in_sizes, int n_in,
                              void* d_out, int out_size)
{
    const float* adj = (const float*)d_in[0];
    const float* W1  = (const float*)d_in[1];
    const float* b1  = (const float*)d_in[2];
    const float* W2  = (const float*)d_in[3];
    const float* b2  = (const float*)d_in[4];
    const float* z   = (const float*)d_in[5];
    float* out = (float*)d_out;

    cudaFuncSetAttribute(gemm2_mma_kernel,
                         cudaFuncAttributeMaxDynamicSharedMemorySize, G2_SMEM);

    // W2 -> bf16 hi/lo (layout preserved, streaming)
    w2conv_kernel<<<(LAT * OUT_DIM / 4) / 256, 256>>>(W2);

    // Layer 1: A = relu(adj @ W1 + b1) -> bf16 hi/lo
    gemm1_kernel<<<dim3(LAT / 64, N_NODE / 64), 256>>>(adj, W1, b1);

    // Layer 2: mma.sync split-bf16 + ldmatrix, K-split partials
    gemm2_mma_kernel<<<dim3(OUT_DIM / BN, N_NODE / BM, KSPLIT), 256, G2_SMEM>>>();

    // p0
    p0_kernel<<<512, 256>>>(b2, z);

    // top-m
    topm_kernel<<<N_NODE, 256>>>(out);
}